// round 3
// baseline (speedup 1.0000x reference)
#include <cuda_runtime.h>
#include <math.h>
#include <float.h>

#define NROWS 32768
#define DIN   768
#define DLAT  256
#define RQ_DEPTH 4
#define KCODES 1024

#define WD       1e-5f   // d-gap window that triggers reference-rounding emulation
#define MAX_CAND 8

// ---------------- scratch (no allocations allowed) ----------------
__device__ float g_h1[NROWS * DLAT];          // encoder hidden / decoder hidden (reused)
__device__ float g_res[NROWS * DLAT];         // residual
__device__ float g_q[NROWS * DLAT];           // running quantized sum
__device__ float g_cnorm[RQ_DEPTH * KCODES];  // ||c||^2 per code (XLA-order fp32 reduce)

// jax exact gelu: x * (erf(x / sqrt(2)) + 1) / 2, fp32 op-for-op
__device__ __forceinline__ float gelu_exact(float x) {
    float t = __fdiv_rn(x, 1.41421354f);            // np.float32(sqrt(2))
    float e = erff(t);
    float u = __fmul_rn(x, __fadd_rn(e, 1.0f));
    return __fmul_rn(u, 0.5f);                      // exact
}

// =====================================================================
// SGEMM: C[M,N] = epi(A[M,K] @ B[K,N] + bias[N])
// BM=128, BN=64, BK=16, 256 threads, 8x4 per-thread tile.
// Sequential-k single FFMA chain per output (bit-matches cuBLAS-style).
// EPI: 0 = bias only; 1 = bias+GELU; 2 = bias, also write C2=val and C3=0
// =====================================================================
template <int EPI>
__global__ __launch_bounds__(256, 4)
void sgemm_kernel(const float* __restrict__ A, const float* __restrict__ B,
                  const float* __restrict__ bias, float* __restrict__ C,
                  float* __restrict__ C2, float* __restrict__ C3,
                  int M, int N, int K)
{
    __shared__ float As[16][132];
    __shared__ float Bs[16][64];

    const int tid = threadIdx.x;
    const int tx = tid & 15;
    const int ty = tid >> 4;
    const int row0 = blockIdx.y * 128;
    const int col0 = blockIdx.x * 64;

    float acc[8][4];
#pragma unroll
    for (int i = 0; i < 8; i++)
#pragma unroll
        for (int j = 0; j < 4; j++) acc[i][j] = 0.0f;

    const int ar = tid >> 2;
    const int ac = (tid & 3) * 4;
    const int br = tid >> 4;
    const int bc = (tid & 15) * 4;

    for (int k0 = 0; k0 < K; k0 += 16) {
        float4 a0 = *(const float4*)(A + (size_t)(row0 + ar) * K + k0 + ac);
        float4 a1 = *(const float4*)(A + (size_t)(row0 + ar + 64) * K + k0 + ac);
        As[ac + 0][ar] = a0.x; As[ac + 1][ar] = a0.y;
        As[ac + 2][ar] = a0.z; As[ac + 3][ar] = a0.w;
        As[ac + 0][ar + 64] = a1.x; As[ac + 1][ar + 64] = a1.y;
        As[ac + 2][ar + 64] = a1.z; As[ac + 3][ar + 64] = a1.w;
        *(float4*)&Bs[br][bc] = *(const float4*)(B + (size_t)(k0 + br) * N + col0 + bc);
        __syncthreads();

#pragma unroll
        for (int k = 0; k < 16; k++) {
            float4 av0 = *(float4*)&As[k][ty * 8];
            float4 av1 = *(float4*)&As[k][ty * 8 + 4];
            float4 bv  = *(float4*)&Bs[k][tx * 4];
            float a[8] = {av0.x, av0.y, av0.z, av0.w, av1.x, av1.y, av1.z, av1.w};
            float b[4] = {bv.x, bv.y, bv.z, bv.w};
#pragma unroll
            for (int i = 0; i < 8; i++)
#pragma unroll
                for (int j = 0; j < 4; j++) acc[i][j] = __fmaf_rn(a[i], b[j], acc[i][j]);
        }
        __syncthreads();
    }

    float4 bb = *(const float4*)(bias + col0 + tx * 4);
#pragma unroll
    for (int i = 0; i < 8; i++) {
        int row = row0 + ty * 8 + i;
        float4 v;
        v.x = __fadd_rn(acc[i][0], bb.x); v.y = __fadd_rn(acc[i][1], bb.y);
        v.z = __fadd_rn(acc[i][2], bb.z); v.w = __fadd_rn(acc[i][3], bb.w);
        if (EPI == 1) {
            v.x = gelu_exact(v.x); v.y = gelu_exact(v.y);
            v.z = gelu_exact(v.z); v.w = gelu_exact(v.w);
        }
        size_t off = (size_t)row * N + col0 + tx * 4;
        *(float4*)(C + off) = v;
        if (EPI == 2) {
            *(float4*)(C2 + off) = v;
            float4 z = {0.f, 0.f, 0.f, 0.f};
            *(float4*)(C3 + off) = z;
        }
    }
}

// =====================================================================
// cnorm: ||c||^2 per code, emulating XLA GPU row-reduce order:
// lane l sums fl(c^2) at cols l, l+32, ..., l+224 sequentially, then
// shuffle tree (offsets 16,8,4,2,1). One warp per code.
// =====================================================================
__global__ void cnorm_kernel(const float* __restrict__ cb) {
    int gw = (blockIdx.x * blockDim.x + threadIdx.x) >> 5;
    int lane = threadIdx.x & 31;
    if (gw >= RQ_DEPTH * KCODES) return;
    const float* r = cb + (size_t)gw * DLAT;
    float s = 0.0f;
#pragma unroll
    for (int j = 0; j < 8; j++) {
        float v = r[lane + 32 * j];
        s = __fadd_rn(s, __fmul_rn(v, v));
    }
#pragma unroll
    for (int o = 16; o; o >>= 1)
        s = __fadd_rn(s, __shfl_down_sync(0xffffffffu, s, o));
    if (lane == 0) g_cnorm[gw] = s;
}

// =====================================================================
// RQ step: 64-row tile, score GEMM (s = cn - 2*r.c, == d - rn, same
// ranking & gaps as d) with per-thread top-2.  Rows whose top-2 gap
// < WD get the reference-rounding emulation:
//   rn   = fp32 row reduce of fl(r^2), XLA warp order
//   rc   = sequential-k fp32 FMA chain
//   d    = fl32( fl32(rn - 2*rc) + cn )
//   argmin with ties -> lowest index
// =====================================================================
__global__ __launch_bounds__(256, 2)
void rq_kernel(const float* __restrict__ cb,      // [KCODES, DLAT] (this depth)
               const float* __restrict__ cnorm,   // [KCODES] (this depth)
               float* __restrict__ res, float* __restrict__ qsum,
               const float* __restrict__ latent,  // for STE on last depth
               float* __restrict__ idx_out,       // [NROWS] (this depth slice)
               float* __restrict__ qout)          // out_quantized or nullptr
{
    extern __shared__ float smem[];
    float* Rs   = smem;                    // 64*260
    float* Cs   = Rs + 64 * 260;           // 16*132
    float* Cn   = Cs + 16 * 132;           // 1024
    float* sval = Cn + 1024;               // 64*34
    int*   sidx = (int*)(sval + 64 * 34);  // 64*34

    const int tid = threadIdx.x;
    const int tx = tid & 15;
    const int ty = tid >> 4;
    const int row0 = blockIdx.x * 64;

    // resident residual tile 64 x 256
#pragma unroll
    for (int m = 0; m < 16; m++) {
        int f = tid + m * 256;
        int r = f >> 6, c4 = f & 63;
        float4 v = *(const float4*)(res + (size_t)(row0 + r) * DLAT + c4 * 4);
        *(float4*)(Rs + r * 260 + c4 * 4) = v;
    }
#pragma unroll
    for (int m = 0; m < 4; m++) Cn[tid + m * 256] = cnorm[tid + m * 256];
    __syncthreads();

    float b1v[4], b2v[4]; int b1i[4], b2i[4];
#pragma unroll
    for (int i = 0; i < 4; i++) { b1v[i] = FLT_MAX; b2v[i] = FLT_MAX; b1i[i] = 0; b2i[i] = 0; }

    for (int tile = 0; tile < 8; tile++) {
        const int cbase = tile * 128;
        float acc[4][8];
#pragma unroll
        for (int i = 0; i < 4; i++)
#pragma unroll
            for (int j = 0; j < 8; j++) acc[i][j] = 0.0f;

        for (int kc = 0; kc < 16; kc++) {
            const int k0 = kc * 16;
#pragma unroll
            for (int m = 0; m < 2; m++) {
                int f = tid + m * 256;
                int code = f >> 2, cw = (f & 3) * 4;
                float4 v = *(const float4*)(cb + (size_t)(cbase + code) * DLAT + k0 + cw);
                Cs[(cw + 0) * 132 + code] = v.x;
                Cs[(cw + 1) * 132 + code] = v.y;
                Cs[(cw + 2) * 132 + code] = v.z;
                Cs[(cw + 3) * 132 + code] = v.w;
            }
            __syncthreads();
#pragma unroll
            for (int k = 0; k < 16; k++) {
                float a[4], b[8];
#pragma unroll
                for (int i = 0; i < 4; i++) a[i] = Rs[(ty * 4 + i) * 260 + k0 + k];
#pragma unroll
                for (int j = 0; j < 8; j++) b[j] = Cs[k * 132 + j * 16 + tx];
#pragma unroll
                for (int i = 0; i < 4; i++)
#pragma unroll
                    for (int j = 0; j < 8; j++) acc[i][j] = __fmaf_rn(a[i], b[j], acc[i][j]);
            }
            __syncthreads();
        }
#pragma unroll
        for (int i = 0; i < 4; i++) {
#pragma unroll
            for (int j = 0; j < 8; j++) {
                int code = cbase + j * 16 + tx;
                float s = __fmaf_rn(-2.0f, acc[i][j], Cn[code]);  // d - rn (exact ranking)
                if (s < b1v[i]) { b2v[i] = b1v[i]; b2i[i] = b1i[i]; b1v[i] = s; b1i[i] = code; }
                else if (s < b2v[i]) { b2v[i] = s; b2i[i] = code; }
            }
        }
    }

#pragma unroll
    for (int i = 0; i < 4; i++) {
        int r = ty * 4 + i;
        sval[r * 34 + 2 * tx]     = b1v[i];
        sidx[r * 34 + 2 * tx]     = b1i[i];
        sval[r * 34 + 2 * tx + 1] = b2v[i];
        sidx[r * 34 + 2 * tx + 1] = b2i[i];
    }
    __syncthreads();

    if (tid < 64) {
        const int r = tid;
        float v1 = FLT_MAX, v2 = FLT_MAX; int i1 = 0x7fffffff;
#pragma unroll
        for (int t = 0; t < 32; t++) {
            float v = sval[r * 34 + t];
            int   ix = sidx[r * 34 + t];
            if (v < v1 || (v == v1 && ix < i1)) { v2 = v1; v1 = v; i1 = ix; }
            else if (v < v2) { v2 = v; }
        }
        int chosen = i1;
        if (v2 - v1 < WD) {
            // collect candidates in the window
            int cidx[MAX_CAND]; int nc = 0;
            for (int t = 0; t < 32 && nc < MAX_CAND; t++) {
                if (sval[r * 34 + t] <= v1 + WD) {
                    int ix = sidx[r * 34 + t];
                    bool dup = false;
                    for (int u = 0; u < nc; u++) if (cidx[u] == ix) dup = true;
                    if (!dup) cidx[nc++] = ix;
                }
            }
            // rn: emulate XLA warp row-reduce (strided-8 + tree)
            float lanes[32];
            const float* rr = Rs + r * 260;
            for (int l = 0; l < 32; l++) {
                float s = 0.0f;
                for (int j = 0; j < 8; j++) {
                    float v = rr[l + 32 * j];
                    s = __fadd_rn(s, __fmul_rn(v, v));
                }
                lanes[l] = s;
            }
            for (int o = 16; o; o >>= 1)
                for (int l = 0; l < o; l++)
                    lanes[l] = __fadd_rn(lanes[l], lanes[l + o]);
            float rn = lanes[0];

            // emulated reference d per candidate; ties -> lowest index
            float bestd = FLT_MAX; int besti = 0x7fffffff;
            for (int u = 0; u < nc; u++) {
                int ix = cidx[u];
                const float* crow = cb + (size_t)ix * DLAT;
                float rc = 0.0f;
                for (int k = 0; k < DLAT; k++)
                    rc = __fmaf_rn(rr[k], crow[k], rc);
                float d = __fadd_rn(__fadd_rn(rn, __fmul_rn(-2.0f, rc)), Cn[ix]);
                if (d < bestd || (d == bestd && ix < besti)) { bestd = d; besti = ix; }
            }
            chosen = besti;
        }
        sidx[r * 34] = chosen;
        idx_out[row0 + r] = (float)chosen;
    }
    __syncthreads();

    // gather q = cb[idx], residual -= q, qsum += q  (+ STE output on last depth)
#pragma unroll
    for (int m = 0; m < 16; m++) {
        int f = tid + m * 256;
        int r = f >> 6, c4 = (f & 63) * 4;
        int code = sidx[r * 34];
        size_t off = (size_t)(row0 + r) * DLAT + c4;
        float4 q = *(const float4*)(cb + (size_t)code * DLAT + c4);
        float4 rv = *(float4*)(Rs + r * 260 + c4);
        rv.x = __fadd_rn(rv.x, -q.x); rv.y = __fadd_rn(rv.y, -q.y);
        rv.z = __fadd_rn(rv.z, -q.z); rv.w = __fadd_rn(rv.w, -q.w);
        *(float4*)(res + off) = rv;
        float4 qs = *(float4*)(qsum + off);
        qs.x = __fadd_rn(qs.x, q.x); qs.y = __fadd_rn(qs.y, q.y);
        qs.z = __fadd_rn(qs.z, q.z); qs.w = __fadd_rn(qs.w, q.w);
        *(float4*)(qsum + off) = qs;
        if (qout) {
            float4 lt = *(const float4*)(latent + off);
            float4 st;
            st.x = __fadd_rn(lt.x, __fadd_rn(qs.x, -lt.x));
            st.y = __fadd_rn(lt.y, __fadd_rn(qs.y, -lt.y));
            st.z = __fadd_rn(lt.z, __fadd_rn(qs.z, -lt.z));
            st.w = __fadd_rn(lt.w, __fadd_rn(qs.w, -lt.w));
            *(float4*)(qout + off) = st;
        }
    }
}

// =====================================================================
// launch
// =====================================================================
extern "C" void kernel_launch(void* const* d_in, const int* in_sizes, int n_in,
                              void* d_out, int out_size)
{
    const float* inputs = (const float*)d_in[0];
    const float* enc_w1 = (const float*)d_in[1];
    const float* enc_b1 = (const float*)d_in[2];
    const float* enc_w2 = (const float*)d_in[3];
    const float* enc_b2 = (const float*)d_in[4];
    const float* codebooks = (const float*)d_in[5];
    const float* dec_w1 = (const float*)d_in[6];
    const float* dec_b1 = (const float*)d_in[7];
    const float* dec_w2 = (const float*)d_in[8];
    const float* dec_b2 = (const float*)d_in[9];

    float* out = (float*)d_out;
    float* out_recon  = out;                                   // [N, 768]
    float* out_idx    = out_recon + (size_t)NROWS * DIN;       // [4, N]
    float* out_latent = out_idx + (size_t)RQ_DEPTH * NROWS;    // [N, 256]
    float* out_quant  = out_latent + (size_t)NROWS * DLAT;     // [N, 256]

    float *h1, *res, *q, *cn;
    cudaGetSymbolAddress((void**)&h1, g_h1);
    cudaGetSymbolAddress((void**)&res, g_res);
    cudaGetSymbolAddress((void**)&q, g_q);
    cudaGetSymbolAddress((void**)&cn, g_cnorm);

    const int RQ_SMEM = (64 * 260 + 16 * 132 + 1024 + 64 * 34) * 4 + 64 * 34 * 4;
    cudaFuncSetAttribute(rq_kernel, cudaFuncAttributeMaxDynamicSharedMemorySize, RQ_SMEM);

    // encoder
    sgemm_kernel<1><<<dim3(DLAT / 64, NROWS / 128), 256>>>(
        inputs, enc_w1, enc_b1, h1, nullptr, nullptr, NROWS, DLAT, DIN);
    sgemm_kernel<2><<<dim3(DLAT / 64, NROWS / 128), 256>>>(
        h1, enc_w2, enc_b2, out_latent, res, q, NROWS, DLAT, DLAT);

    // code norms (all depths, XLA reduce order)
    cnorm_kernel<<<(RQ_DEPTH * KCODES * 32) / 256, 256>>>(codebooks);

    // residual quantization
    for (int d = 0; d < RQ_DEPTH; d++) {
        rq_kernel<<<NROWS / 64, 256, RQ_SMEM>>>(
            codebooks + (size_t)d * KCODES * DLAT,
            cn + (size_t)d * KCODES,
            res, q, out_latent,
            out_idx + (size_t)d * NROWS,
            (d == RQ_DEPTH - 1) ? out_quant : nullptr);
    }

    // decoder (reads the STE quantized values, as reference does)
    sgemm_kernel<1><<<dim3(DLAT / 64, NROWS / 128), 256>>>(
        out_quant, dec_w1, dec_b1, h1, nullptr, nullptr, NROWS, DLAT, DLAT);
    sgemm_kernel<0><<<dim3(DIN / 64, NROWS / 128), 256>>>(
        h1, dec_w2, dec_b2, out_recon, nullptr, nullptr, NROWS, DIN, DLAT);
}